// round 9
// baseline (speedup 1.0000x reference)
#include <cuda_runtime.h>
#include <cuda_bf16.h>
#include <math.h>
#include <stdint.h>

// Problem constants
#define T_  256
#define B_  64
#define I_  1024
#define L_  2
#define G_  4
#define H_  1024
#define R_  16

#define N_TOT  (G_ * H_)
#define K_HALF 1024

// GEMM config: grid (32 M-tiles, 8 k-splits), 256 thr, 2 CTA/SM
#define KS     8
#define KSLICE 256             // K per split
#define MT     128             // M rows per CTA
#define NSTEP  (KSLICE / 16)   // 16 k16 steps
#define PF     3               // W prefetch depth (validated)

// Scratch
__device__ float g_pre[KS * N_TOT * B_];   // [ks][m][b]  8 MB
__device__ float g_u[2 * G_ * R_ * B_];    // [src][g][r][b]  (b fast)

#define SWZ(o) ((o) ^ (((o) >> 3) & 0x70))

__device__ __forceinline__ uint32_t smem_u32(const void* p) {
    uint32_t a;
    asm("{ .reg .u64 t; cvta.to.shared.u64 t, %1; cvt.u32.u64 %0, t; }" : "=r"(a) : "l"(p));
    return a;
}
__device__ __forceinline__ void cvt_hilo(float a, float b, uint32_t& hi, uint32_t& lo) {
    __nv_bfloat162 h = __floats2bfloat162_rn(a, b);
    float ra = a - __bfloat162float(h.x);
    float rb = b - __bfloat162float(h.y);
    __nv_bfloat162 l = __floats2bfloat162_rn(ra, rb);
    hi = *(uint32_t*)&h;
    lo = *(uint32_t*)&l;
}
__device__ __forceinline__ void ldsm4(uint32_t* r, uint32_t addr) {
    asm volatile("ldmatrix.sync.aligned.m8n8.x4.shared.b16 {%0,%1,%2,%3}, [%4];"
                 : "=r"(r[0]), "=r"(r[1]), "=r"(r[2]), "=r"(r[3]) : "r"(addr));
}
__device__ __forceinline__ void mma_bf16(float* d, const uint32_t* a, uint32_t b0, uint32_t b1) {
    asm volatile("mma.sync.aligned.m16n8k16.row.col.f32.bf16.bf16.f32 "
                 "{%0,%1,%2,%3}, {%4,%5,%6,%7}, {%8,%9}, {%0,%1,%2,%3};"
                 : "+f"(d[0]), "+f"(d[1]), "+f"(d[2]), "+f"(d[3])
                 : "r"(a[0]), "r"(a[1]), "r"(a[2]), "r"(a[3]), "r"(b0), "r"(b1));
}

// ---------------------------------------------------------------------------
// Fused kernel: (a) rank-16 LoRA projections (hidden under the W stream),
// (b) HMMA split-K GEMM, bf16 3-term split precision, 3-deep W prefetch.
// (R6/R8-validated configuration — unchanged.)
// ---------------------------------------------------------------------------
__global__ void __launch_bounds__(256, 2)
gemm_mma_kernel(const float* __restrict__ x, const float* __restrict__ h0,
                const float* __restrict__ W_x, const float* __restrict__ W_h,
                const float* __restrict__ A_x, const float* __restrict__ A_h,
                int l)
{
    __shared__ __align__(1024) uint8_t sx_hi[8192];   // x chunk: 64 n x 64 k bf16, SWZ
    __shared__ __align__(1024) uint8_t sx_lo[8192];

    const int tid  = threadIdx.x;
    const int wid  = tid >> 5;
    const int lane = tid & 31;
    const int ks   = blockIdx.y;
    const int m0   = blockIdx.x * MT;

    const float* Wbase;
    const float* vbase;
    int koff;
    if (ks < 4) { Wbase = W_x + (size_t)l * N_TOT * K_HALF; vbase = x;
                  koff = ks * KSLICE; }
    else        { Wbase = W_h + (size_t)l * N_TOT * K_HALF; vbase = h0 + (size_t)l * B_ * H_;
                  koff = (ks - 4) * KSLICE; }

    const int g = lane >> 2;
    const int q = lane & 3;

    const float* WA = Wbase + (size_t)(m0 + wid * 16 + g) * K_HALF + koff;
    const float* WB = WA + 8 * (size_t)K_HALF;

    // -------- issue first PF steps of W loads immediately --------
    float2 wbufA0[PF], wbufA1[PF], wbufB0[PF], wbufB1[PF];
#pragma unroll
    for (int s = 0; s < PF; ++s) {
        const int kk = s * 16 + 2 * q;
        wbufA0[s] = *(const float2*)(WA + kk);
        wbufA1[s] = *(const float2*)(WA + kk + 8);
        wbufB0[s] = *(const float2*)(WB + kk);
        wbufB1[s] = *(const float2*)(WB + kk + 8);
    }

    // -------- LoRA projections (while W loads are in flight) --------
    {
        const uint32_t wg = ((uint32_t)blockIdx.y * 32u + blockIdx.x) * 8u + wid;
#pragma unroll
        for (int t = 0; t < 2; ++t) {
            const uint32_t task = wg * 2u + t;      // 0..4095
            const int src  = task >> 11;
            const int rem  = task & 2047;
            const int gg   = rem >> 9;
            const int rem2 = rem & 511;
            const int b    = rem2 >> 3;
            const int rp   = rem2 & 7;

            const float* vec = (src == 0) ? (x + (size_t)b * I_)
                                          : (h0 + (size_t)l * B_ * H_ + (size_t)b * H_);
            const float* A = ((src == 0) ? A_x : A_h) + ((size_t)(l * G_ + gg)) * R_ * K_HALF;
            const float4* v4 = (const float4*)vec;
            const float4* a0 = (const float4*)(A + (size_t)(rp * 2) * K_HALF);
            const float4* a1 = (const float4*)(A + (size_t)(rp * 2 + 1) * K_HALF);

            float acc0 = 0.f, acc1 = 0.f;
#pragma unroll
            for (int j = 0; j < 8; ++j) {
                const int i4 = j * 32 + lane;
                float4 v = v4[i4];
                float4 a = a0[i4];
                float4 c = a1[i4];
                acc0 += v.x * a.x + v.y * a.y + v.z * a.z + v.w * a.w;
                acc1 += v.x * c.x + v.y * c.y + v.z * c.z + v.w * c.w;
            }
#pragma unroll
            for (int off = 16; off > 0; off >>= 1) {
                acc0 += __shfl_down_sync(0xffffffffu, acc0, off);
                acc1 += __shfl_down_sync(0xffffffffu, acc1, off);
            }
            if (lane == 0) {
                float* u = &g_u[((size_t)(src * G_ + gg) * R_) * B_ + b];
                u[(size_t)(rp * 2) * B_]     = acc0;
                u[(size_t)(rp * 2 + 1) * B_] = acc1;
            }
        }
    }

    // -------- x staging geometry --------
    const int xn = tid >> 2;
    const int xq = tid & 3;
    const float* Xsrc = vbase + (size_t)xn * K_HALF + koff + xq * 16;
    uint32_t st_off[4];
#pragma unroll
    for (int j = 0; j < 4; ++j) {
        uint32_t o = (uint32_t)xn * 128u + (uint32_t)xq * 32u + (uint32_t)j * 8u;
        st_off[j] = SWZ(o);
    }

    // ldmatrix lane geometry
    const int lm_row  = 8 * ((lane >> 4) & 1) + (lane & 7);
    const int lm_kb   = ((lane >> 3) & 1) * 16;
    const int cswz    = (lane & 7) << 4;
    const uint32_t rowoff = (uint32_t)lm_row * 128u;
    const uint32_t hi_base = smem_u32(sx_hi);
    const uint32_t lo_base = smem_u32(sx_lo);

    float acc[8][4];
#pragma unroll
    for (int t = 0; t < 8; ++t)
#pragma unroll
        for (int j = 0; j < 4; ++j) acc[t][j] = 0.f;

#pragma unroll
    for (int step = 0; step < NSTEP; ++step) {
        if ((step & 3) == 0) {                 // stage next 64-k chunk of x
            if (step) __syncthreads();
            const float4* s4 = (const float4*)(Xsrc + (step >> 2) * 64);
#pragma unroll
            for (int j = 0; j < 4; ++j) {
                float4 f = s4[j];
                uint32_t h01, l01, h23, l23;
                cvt_hilo(f.x, f.y, h01, l01);
                cvt_hilo(f.z, f.w, h23, l23);
                *(uint2*)(sx_hi + st_off[j]) = make_uint2(h01, h23);
                *(uint2*)(sx_lo + st_off[j]) = make_uint2(l01, l23);
            }
            __syncthreads();
        }

        const int cur = step % PF;             // static under full unroll

        uint32_t a_hi[4], a_lo[4];
        cvt_hilo(wbufA0[cur].x, wbufA0[cur].y, a_hi[0], a_lo[0]);
        cvt_hilo(wbufB0[cur].x, wbufB0[cur].y, a_hi[1], a_lo[1]);
        cvt_hilo(wbufA1[cur].x, wbufA1[cur].y, a_hi[2], a_lo[2]);
        cvt_hilo(wbufB1[cur].x, wbufB1[cur].y, a_hi[3], a_lo[3]);

        if (step + PF < NSTEP) {               // refill the freed slot
            const int kk = (step + PF) * 16 + 2 * q;
            wbufA0[cur] = *(const float2*)(WA + kk);
            wbufA1[cur] = *(const float2*)(WA + kk + 8);
            wbufB0[cur] = *(const float2*)(WB + kk);
            wbufB1[cur] = *(const float2*)(WB + kk + 8);
        }

        const int kb = lm_kb + (step & 3) * 32;
        const uint32_t koffsw = (uint32_t)(kb ^ cswz);

#pragma unroll
        for (int tp = 0; tp < 4; ++tp) {
            const uint32_t off = rowoff + (uint32_t)tp * 2048u + koffsw;
            uint32_t bh[4], bl[4];
            ldsm4(bh, hi_base + off);
            ldsm4(bl, lo_base + off);
            mma_bf16(acc[2 * tp],     a_hi, bh[0], bh[1]);
            mma_bf16(acc[2 * tp],     a_hi, bl[0], bl[1]);
            mma_bf16(acc[2 * tp],     a_lo, bh[0], bh[1]);
            mma_bf16(acc[2 * tp + 1], a_hi, bh[2], bh[3]);
            mma_bf16(acc[2 * tp + 1], a_hi, bl[2], bl[3]);
            mma_bf16(acc[2 * tp + 1], a_lo, bh[2], bh[3]);
        }
    }

    // epilogue
    float* base0 = &g_pre[((size_t)ks * N_TOT + m0 + wid * 16 + g) * B_];
    float* base8 = base0 + 8 * B_;
#pragma unroll
    for (int t = 0; t < 8; ++t) {
        *(float2*)(base0 + t * 8 + 2 * q) = make_float2(acc[t][0], acc[t][1]);
        *(float2*)(base8 + t * 8 + 2 * q) = make_float2(acc[t][2], acc[t][3]);
    }
}

// ---------------------------------------------------------------------------
// Gates v4: block = 64 threads (grid 512). Thread = (gate gg, b-quad) handling
// 4 consecutive b and BOTH h of the block's h-pair. ALL global loads are
// LDG.128: g_pre partials (16), g_u rank vectors (32, reused for both h),
// B_x/B_h rank rows (16). ~8.6 loads/output vs 58 in v3.
// ---------------------------------------------------------------------------
__global__ void __launch_bounds__(64)
gates_kernel(const float* __restrict__ b_x,
             const float* __restrict__ b_h,
             const float* __restrict__ B_x,
             const float* __restrict__ B_h,
             const float* __restrict__ c0,
             float* __restrict__ out,
             int l)
{
    __shared__ float sp[G_][2][B_];

    const int h0 = blockIdx.x * 2;
    const int gg = threadIdx.x >> 4;          // 0..3
    const int b4 = (threadIdx.x & 15) * 4;    // 0,4,...,60

    const float bias0 = b_x[(l * G_ + gg) * H_ + h0]     + b_h[(l * G_ + gg) * H_ + h0];
    const float bias1 = b_x[(l * G_ + gg) * H_ + h0 + 1] + b_h[(l * G_ + gg) * H_ + h0 + 1];

    float4 a0 = make_float4(bias0, bias0, bias0, bias0);
    float4 a1 = make_float4(bias1, bias1, bias1, bias1);

    // ---- split-K partials: 16 x LDG.128 ----
    const float* p = &g_pre[((size_t)gg * H_ + h0) * B_ + b4];
#pragma unroll
    for (int ks = 0; ks < KS; ++ks) {
        float4 q0 = *(const float4*)(p + (size_t)ks * N_TOT * B_);
        float4 q1 = *(const float4*)(p + (size_t)ks * N_TOT * B_ + B_);
        a0.x += q0.x; a0.y += q0.y; a0.z += q0.z; a0.w += q0.w;
        a1.x += q1.x; a1.y += q1.y; a1.z += q1.z; a1.w += q1.w;
    }

    // ---- LoRA: B rows as float4 (rows h0 and h0+1 are contiguous 32 floats) ----
    const float4* Bx4 = (const float4*)(B_x + ((size_t)((l * G_ + gg) * H_) + h0) * R_);
    const float4* Bh4 = (const float4*)(B_h + ((size_t)((l * G_ + gg) * H_) + h0) * R_);
    float4 bx0[4], bx1[4], bhv0[4], bhv1[4];
#pragma unroll
    for (int j = 0; j < 4; ++j) {
        bx0[j]  = Bx4[j];     bx1[j]  = Bx4[4 + j];
        bhv0[j] = Bh4[j];     bhv1[j] = Bh4[4 + j];
    }

    const float4* ux = (const float4*)(g_u + ((size_t)(0 * G_ + gg) * R_) * B_ + b4);
    const float4* uh = (const float4*)(g_u + ((size_t)(1 * G_ + gg) * R_) * B_ + b4);

#pragma unroll
    for (int r = 0; r < R_; ++r) {
        const float4 u = ux[r * (B_ / 4)];
        const float c0f = (&bx0[r >> 2].x)[r & 3];
        const float c1f = (&bx1[r >> 2].x)[r & 3];
        a0.x += c0f * u.x; a0.y += c0f * u.y; a0.z += c0f * u.z; a0.w += c0f * u.w;
        a1.x += c1f * u.x; a1.y += c1f * u.y; a1.z += c1f * u.z; a1.w += c1f * u.w;
    }
#pragma unroll
    for (int r = 0; r < R_; ++r) {
        const float4 u = uh[r * (B_ / 4)];
        const float c0f = (&bhv0[r >> 2].x)[r & 3];
        const float c1f = (&bhv1[r >> 2].x)[r & 3];
        a0.x += c0f * u.x; a0.y += c0f * u.y; a0.z += c0f * u.z; a0.w += c0f * u.w;
        a1.x += c1f * u.x; a1.y += c1f * u.y; a1.z += c1f * u.z; a1.w += c1f * u.w;
    }

    *(float4*)&sp[gg][0][b4] = a0;
    *(float4*)&sp[gg][1][b4] = a1;
    __syncthreads();

    // ---- activation tail: thread = b, two h values, float2 I/O ----
    {
        const int b = threadIdx.x;             // 0..63
        float hn[2], cn[2];
        const float2 cv = *(const float2*)&c0[(size_t)l * B_ * H_ + (size_t)b * H_ + h0];
#pragma unroll
        for (int hh = 0; hh < 2; ++hh) {
            const float i_t = 1.f / (1.f + expf(-sp[0][hh][b]));
            const float f_t = 1.f / (1.f + expf(-sp[1][hh][b]));
            const float g_t = tanhf(sp[2][hh][b]);
            const float o_t = 1.f / (1.f + expf(-sp[3][hh][b]));
            const float c_in = hh ? cv.y : cv.x;
            cn[hh] = f_t * c_in + i_t * g_t;
            hn[hh] = o_t * tanhf(cn[hh]);
        }
        const size_t idx = (size_t)b * H_ + h0;
        *(float2*)&out[(size_t)B_ * H_ * (1 + l) + idx] = make_float2(hn[0], hn[1]);
        *(float2*)&out[(size_t)B_ * H_ * (3 + l) + idx] = make_float2(cn[0], cn[1]);
        if (l == 1)
            *(float2*)&out[idx] = make_float2(hn[0], hn[1]);
    }
}

// ---------------------------------------------------------------------------
extern "C" void kernel_launch(void* const* d_in, const int* in_sizes, int n_in,
                              void* d_out, int out_size)
{
    const float* input_seq = (const float*)d_in[0];
    const float* h0        = (const float*)d_in[1];
    const float* c0        = (const float*)d_in[2];
    const float* W_x       = (const float*)d_in[3];
    const float* W_h       = (const float*)d_in[4];
    const float* b_x       = (const float*)d_in[5];
    const float* b_h       = (const float*)d_in[6];
    const float* A_x       = (const float*)d_in[7];
    const float* B_x       = (const float*)d_in[8];
    const float* A_h       = (const float*)d_in[9];
    const float* B_h       = (const float*)d_in[10];
    float* out = (float*)d_out;

    const float* x_last = input_seq + (size_t)(T_ - 1) * B_ * I_;

    for (int l = 0; l < L_; ++l) {
        const float* x = (l == 0) ? x_last : (out + (size_t)B_ * H_);  // h_t[0]

        gemm_mma_kernel<<<dim3(N_TOT / MT, KS), 256>>>(x, h0, W_x, W_h, A_x, A_h, l);
        gates_kernel<<<H_ / 2, 64>>>(b_x, b_h, B_x, B_h, c0, out, l);
    }
}

// round 10
// speedup vs baseline: 1.0789x; 1.0789x over previous
#include <cuda_runtime.h>
#include <cuda_bf16.h>
#include <math.h>
#include <stdint.h>

// Problem constants
#define T_  256
#define B_  64
#define I_  1024
#define L_  2
#define G_  4
#define H_  1024
#define R_  16

#define N_TOT  (G_ * H_)
#define K_HALF 1024

// GEMM config: grid (32 M-tiles, 8 k-splits), 256 thr, 2 CTA/SM
#define KS     8
#define KSLICE 256             // K per split
#define MT     128             // M rows per CTA
#define NSTEP  (KSLICE / 16)   // 16 k16 steps
#define PF     3               // W prefetch depth (validated)

// Scratch
__device__ float g_pre[KS * N_TOT * B_];   // [ks][m][b]  8 MB
__device__ float g_u[2 * G_ * R_ * B_];    // [src][g][r][b]  (b fast)

#define SWZ(o) ((o) ^ (((o) >> 3) & 0x70))

__device__ __forceinline__ uint32_t smem_u32(const void* p) {
    uint32_t a;
    asm("{ .reg .u64 t; cvta.to.shared.u64 t, %1; cvt.u32.u64 %0, t; }" : "=r"(a) : "l"(p));
    return a;
}
__device__ __forceinline__ void cvt_hilo(float a, float b, uint32_t& hi, uint32_t& lo) {
    __nv_bfloat162 h = __floats2bfloat162_rn(a, b);
    float ra = a - __bfloat162float(h.x);
    float rb = b - __bfloat162float(h.y);
    __nv_bfloat162 l = __floats2bfloat162_rn(ra, rb);
    hi = *(uint32_t*)&h;
    lo = *(uint32_t*)&l;
}
__device__ __forceinline__ void ldsm4(uint32_t* r, uint32_t addr) {
    asm volatile("ldmatrix.sync.aligned.m8n8.x4.shared.b16 {%0,%1,%2,%3}, [%4];"
                 : "=r"(r[0]), "=r"(r[1]), "=r"(r[2]), "=r"(r[3]) : "r"(addr));
}
__device__ __forceinline__ void mma_bf16(float* d, const uint32_t* a, uint32_t b0, uint32_t b1) {
    asm volatile("mma.sync.aligned.m16n8k16.row.col.f32.bf16.bf16.f32 "
                 "{%0,%1,%2,%3}, {%4,%5,%6,%7}, {%8,%9}, {%0,%1,%2,%3};"
                 : "+f"(d[0]), "+f"(d[1]), "+f"(d[2]), "+f"(d[3])
                 : "r"(a[0]), "r"(a[1]), "r"(a[2]), "r"(a[3]), "r"(b0), "r"(b1));
}

// ---------------------------------------------------------------------------
// Fused kernel: (a) rank-16 LoRA projections (hidden under the W stream),
// (b) HMMA split-K GEMM, bf16 3-term split precision, 3-deep W prefetch.
// (R6/R8-validated configuration — unchanged.)
// ---------------------------------------------------------------------------
__global__ void __launch_bounds__(256, 2)
gemm_mma_kernel(const float* __restrict__ x, const float* __restrict__ h0,
                const float* __restrict__ W_x, const float* __restrict__ W_h,
                const float* __restrict__ A_x, const float* __restrict__ A_h,
                int l)
{
    __shared__ __align__(1024) uint8_t sx_hi[8192];   // x chunk: 64 n x 64 k bf16, SWZ
    __shared__ __align__(1024) uint8_t sx_lo[8192];

    const int tid  = threadIdx.x;
    const int wid  = tid >> 5;
    const int lane = tid & 31;
    const int ks   = blockIdx.y;
    const int m0   = blockIdx.x * MT;

    const float* Wbase;
    const float* vbase;
    int koff;
    if (ks < 4) { Wbase = W_x + (size_t)l * N_TOT * K_HALF; vbase = x;
                  koff = ks * KSLICE; }
    else        { Wbase = W_h + (size_t)l * N_TOT * K_HALF; vbase = h0 + (size_t)l * B_ * H_;
                  koff = (ks - 4) * KSLICE; }

    const int g = lane >> 2;
    const int q = lane & 3;

    const float* WA = Wbase + (size_t)(m0 + wid * 16 + g) * K_HALF + koff;
    const float* WB = WA + 8 * (size_t)K_HALF;

    // -------- issue first PF steps of W loads immediately --------
    float2 wbufA0[PF], wbufA1[PF], wbufB0[PF], wbufB1[PF];
#pragma unroll
    for (int s = 0; s < PF; ++s) {
        const int kk = s * 16 + 2 * q;
        wbufA0[s] = *(const float2*)(WA + kk);
        wbufA1[s] = *(const float2*)(WA + kk + 8);
        wbufB0[s] = *(const float2*)(WB + kk);
        wbufB1[s] = *(const float2*)(WB + kk + 8);
    }

    // -------- LoRA projections (while W loads are in flight) --------
    {
        const uint32_t wg = ((uint32_t)blockIdx.y * 32u + blockIdx.x) * 8u + wid;
#pragma unroll
        for (int t = 0; t < 2; ++t) {
            const uint32_t task = wg * 2u + t;      // 0..4095
            const int src  = task >> 11;
            const int rem  = task & 2047;
            const int gg   = rem >> 9;
            const int rem2 = rem & 511;
            const int b    = rem2 >> 3;
            const int rp   = rem2 & 7;

            const float* vec = (src == 0) ? (x + (size_t)b * I_)
                                          : (h0 + (size_t)l * B_ * H_ + (size_t)b * H_);
            const float* A = ((src == 0) ? A_x : A_h) + ((size_t)(l * G_ + gg)) * R_ * K_HALF;
            const float4* v4 = (const float4*)vec;
            const float4* a0 = (const float4*)(A + (size_t)(rp * 2) * K_HALF);
            const float4* a1 = (const float4*)(A + (size_t)(rp * 2 + 1) * K_HALF);

            float acc0 = 0.f, acc1 = 0.f;
#pragma unroll
            for (int j = 0; j < 8; ++j) {
                const int i4 = j * 32 + lane;
                float4 v = v4[i4];
                float4 a = a0[i4];
                float4 c = a1[i4];
                acc0 += v.x * a.x + v.y * a.y + v.z * a.z + v.w * a.w;
                acc1 += v.x * c.x + v.y * c.y + v.z * c.z + v.w * c.w;
            }
#pragma unroll
            for (int off = 16; off > 0; off >>= 1) {
                acc0 += __shfl_down_sync(0xffffffffu, acc0, off);
                acc1 += __shfl_down_sync(0xffffffffu, acc1, off);
            }
            if (lane == 0) {
                float* u = &g_u[((size_t)(src * G_ + gg) * R_) * B_ + b];
                u[(size_t)(rp * 2) * B_]     = acc0;
                u[(size_t)(rp * 2 + 1) * B_] = acc1;
            }
        }
    }

    // -------- x staging geometry --------
    const int xn = tid >> 2;
    const int xq = tid & 3;
    const float* Xsrc = vbase + (size_t)xn * K_HALF + koff + xq * 16;
    uint32_t st_off[4];
#pragma unroll
    for (int j = 0; j < 4; ++j) {
        uint32_t o = (uint32_t)xn * 128u + (uint32_t)xq * 32u + (uint32_t)j * 8u;
        st_off[j] = SWZ(o);
    }

    // ldmatrix lane geometry
    const int lm_row  = 8 * ((lane >> 4) & 1) + (lane & 7);
    const int lm_kb   = ((lane >> 3) & 1) * 16;
    const int cswz    = (lane & 7) << 4;
    const uint32_t rowoff = (uint32_t)lm_row * 128u;
    const uint32_t hi_base = smem_u32(sx_hi);
    const uint32_t lo_base = smem_u32(sx_lo);

    float acc[8][4];
#pragma unroll
    for (int t = 0; t < 8; ++t)
#pragma unroll
        for (int j = 0; j < 4; ++j) acc[t][j] = 0.f;

#pragma unroll
    for (int step = 0; step < NSTEP; ++step) {
        if ((step & 3) == 0) {                 // stage next 64-k chunk of x
            if (step) __syncthreads();
            const float4* s4 = (const float4*)(Xsrc + (step >> 2) * 64);
#pragma unroll
            for (int j = 0; j < 4; ++j) {
                float4 f = s4[j];
                uint32_t h01, l01, h23, l23;
                cvt_hilo(f.x, f.y, h01, l01);
                cvt_hilo(f.z, f.w, h23, l23);
                *(uint2*)(sx_hi + st_off[j]) = make_uint2(h01, h23);
                *(uint2*)(sx_lo + st_off[j]) = make_uint2(l01, l23);
            }
            __syncthreads();
        }

        const int cur = step % PF;             // static under full unroll

        uint32_t a_hi[4], a_lo[4];
        cvt_hilo(wbufA0[cur].x, wbufA0[cur].y, a_hi[0], a_lo[0]);
        cvt_hilo(wbufB0[cur].x, wbufB0[cur].y, a_hi[1], a_lo[1]);
        cvt_hilo(wbufA1[cur].x, wbufA1[cur].y, a_hi[2], a_lo[2]);
        cvt_hilo(wbufB1[cur].x, wbufB1[cur].y, a_hi[3], a_lo[3]);

        if (step + PF < NSTEP) {               // refill the freed slot
            const int kk = (step + PF) * 16 + 2 * q;
            wbufA0[cur] = *(const float2*)(WA + kk);
            wbufA1[cur] = *(const float2*)(WA + kk + 8);
            wbufB0[cur] = *(const float2*)(WB + kk);
            wbufB1[cur] = *(const float2*)(WB + kk + 8);
        }

        const int kb = lm_kb + (step & 3) * 32;
        const uint32_t koffsw = (uint32_t)(kb ^ cswz);

#pragma unroll
        for (int tp = 0; tp < 4; ++tp) {
            const uint32_t off = rowoff + (uint32_t)tp * 2048u + koffsw;
            uint32_t bh[4], bl[4];
            ldsm4(bh, hi_base + off);
            ldsm4(bl, lo_base + off);
            mma_bf16(acc[2 * tp],     a_hi, bh[0], bh[1]);
            mma_bf16(acc[2 * tp],     a_hi, bl[0], bl[1]);
            mma_bf16(acc[2 * tp],     a_lo, bh[0], bh[1]);
            mma_bf16(acc[2 * tp + 1], a_hi, bh[2], bh[3]);
            mma_bf16(acc[2 * tp + 1], a_hi, bl[2], bl[3]);
            mma_bf16(acc[2 * tp + 1], a_lo, bh[2], bh[3]);
        }
    }

    // epilogue
    float* base0 = &g_pre[((size_t)ks * N_TOT + m0 + wid * 16 + g) * B_];
    float* base8 = base0 + 8 * B_;
#pragma unroll
    for (int t = 0; t < 8; ++t) {
        *(float2*)(base0 + t * 8 + 2 * q) = make_float2(acc[t][0], acc[t][1]);
        *(float2*)(base8 + t * 8 + 2 * q) = make_float2(acc[t][2], acc[t][3]);
    }
}

// ---------------------------------------------------------------------------
// Gates v5: grid 256 blocks x 256 threads; block owns 4 h values.
// g_u staged to smem once per block (coalesced), rank vectors read via
// LDS.128; g_pre via float4; B rows via float4 broadcast; coalesced float4
// epilogue through a smem transpose.
// Thread = (gate gg, h-of-4 hh, b-quad) -> 4 outputs.
// ---------------------------------------------------------------------------
__global__ void __launch_bounds__(256)
gates_kernel(const float* __restrict__ b_x,
             const float* __restrict__ b_h,
             const float* __restrict__ B_x,
             const float* __restrict__ B_h,
             const float* __restrict__ c0,
             float* __restrict__ out,
             int l)
{
    __shared__ float su[2 * G_ * R_ * B_];    // 32 KB staged g_u
    __shared__ float sp[G_][4][B_];           // 4 KB pre-activations
    __shared__ float sh_h[B_][4];             // epilogue transpose
    __shared__ float sh_c[B_][4];

    const int tid = threadIdx.x;
    const int h0  = blockIdx.x * 4;

    // ---- stage g_u (fully coalesced, 8 x LDG.128 per thread) ----
    {
        const float4* src = (const float4*)g_u;
        float4* dst = (float4*)su;
#pragma unroll
        for (int j = 0; j < 8; ++j)
            dst[tid + j * 256] = src[tid + j * 256];
    }
    __syncthreads();

    // ---- main: (gg, hh, b4) ----
    const int gg  = tid >> 6;
    const int rem = tid & 63;
    const int hh  = rem >> 4;
    const int b4  = (rem & 15) * 4;
    const int h   = h0 + hh;

    const float bias = b_x[(l * G_ + gg) * H_ + h] + b_h[(l * G_ + gg) * H_ + h];
    float4 a = make_float4(bias, bias, bias, bias);

    // split-K partials: 8 x LDG.128
    const float* p = &g_pre[((size_t)gg * H_ + h) * B_ + b4];
#pragma unroll
    for (int ks = 0; ks < KS; ++ks) {
        float4 q = *(const float4*)(p + (size_t)ks * N_TOT * B_);
        a.x += q.x; a.y += q.y; a.z += q.z; a.w += q.w;
    }

    // LoRA B rows: 8 x LDG.128 (broadcast within 16-lane groups)
    const float4* Bx4 = (const float4*)(B_x + ((size_t)((l * G_ + gg) * H_) + h) * R_);
    const float4* Bh4 = (const float4*)(B_h + ((size_t)((l * G_ + gg) * H_) + h) * R_);
    float4 cx[4], ch[4];
#pragma unroll
    for (int j = 0; j < 4; ++j) { cx[j] = Bx4[j]; ch[j] = Bh4[j]; }

    // rank contraction from smem (conflict-free / broadcast LDS.128)
    const float* sux = su + ((size_t)(0 * G_ + gg) * R_) * B_ + b4;
    const float* suh = su + ((size_t)(1 * G_ + gg) * R_) * B_ + b4;
#pragma unroll
    for (int r = 0; r < R_; ++r) {
        const float4 u = *(const float4*)(sux + r * B_);
        const float c = (&cx[r >> 2].x)[r & 3];
        a.x += c * u.x; a.y += c * u.y; a.z += c * u.z; a.w += c * u.w;
    }
#pragma unroll
    for (int r = 0; r < R_; ++r) {
        const float4 u = *(const float4*)(suh + r * B_);
        const float c = (&ch[r >> 2].x)[r & 3];
        a.x += c * u.x; a.y += c * u.y; a.z += c * u.z; a.w += c * u.w;
    }

    *(float4*)&sp[gg][hh][b4] = a;
    __syncthreads();

    // ---- activation: thread = (b, h-of-4), 1 output each ----
    {
        const int b  = tid & 63;
        const int hp = tid >> 6;
        const int hA = h0 + hp;

        const float i_t = 1.f / (1.f + expf(-sp[0][hp][b]));
        const float f_t = 1.f / (1.f + expf(-sp[1][hp][b]));
        const float g_t = tanhf(sp[2][hp][b]);
        const float o_t = 1.f / (1.f + expf(-sp[3][hp][b]));

        const float cv   = c0[(size_t)l * B_ * H_ + (size_t)b * H_ + hA];
        const float cnew = f_t * cv + i_t * g_t;
        const float hnew = o_t * tanhf(cnew);

        sh_h[b][hp] = hnew;
        sh_c[b][hp] = cnew;
    }
    __syncthreads();

    // ---- coalesced stores: 64 threads, float4 (h-contiguous) ----
    if (tid < 64) {
        const int b = tid;
        const float4 h4 = *(const float4*)&sh_h[b][0];
        const float4 c4 = *(const float4*)&sh_c[b][0];
        const size_t idx = (size_t)b * H_ + h0;
        *(float4*)&out[(size_t)B_ * H_ * (1 + l) + idx] = h4;   // h_t[l]
        *(float4*)&out[(size_t)B_ * H_ * (3 + l) + idx] = c4;   // c_t[l]
        if (l == 1)
            *(float4*)&out[idx] = h4;                           // out == h_t[1]
    }
}

// ---------------------------------------------------------------------------
extern "C" void kernel_launch(void* const* d_in, const int* in_sizes, int n_in,
                              void* d_out, int out_size)
{
    const float* input_seq = (const float*)d_in[0];
    const float* h0        = (const float*)d_in[1];
    const float* c0        = (const float*)d_in[2];
    const float* W_x       = (const float*)d_in[3];
    const float* W_h       = (const float*)d_in[4];
    const float* b_x       = (const float*)d_in[5];
    const float* b_h       = (const float*)d_in[6];
    const float* A_x       = (const float*)d_in[7];
    const float* B_x       = (const float*)d_in[8];
    const float* A_h       = (const float*)d_in[9];
    const float* B_h       = (const float*)d_in[10];
    float* out = (float*)d_out;

    const float* x_last = input_seq + (size_t)(T_ - 1) * B_ * I_;

    for (int l = 0; l < L_; ++l) {
        const float* x = (l == 0) ? x_last : (out + (size_t)B_ * H_);  // h_t[0]

        gemm_mma_kernel<<<dim3(N_TOT / MT, KS), 256>>>(x, h0, W_x, W_h, A_x, A_h, l);
        gates_kernel<<<H_ / 4, 256>>>(b_x, b_h, B_x, B_h, c0, out, l);
    }
}